// round 16
// baseline (speedup 1.0000x reference)
#include <cuda_runtime.h>
#include <cstdint>

// Covariance over time axis: x [64, 4, 8192, 16] fp32 -> cov [64, 4, 16, 16]
// cov = (Sum_t x_m x_n - s_m s_n / T) / (T-1)
//
// Single kernel: 256 slices x 4 T-chunks = 1024 CTAs (320 thr = 10 warps).
// Warp w owns upper-triangle 4x4 block (bi,bj); lanes own time-rows.
// Inner loop uses packed f32x2 FMAs (FFMA2). Partials go to __device__ scratch;
// the last CTA per slice (atomicInc, self-resetting) folds 4 chunk partials,
// applies the mean correction, mirrors the triangle, writes the output.
// Deterministic: integer atomic only selects WHO folds; fold order is fixed.

#define T_TOTAL   8192
#define M_DIM     16
#define NCHUNK    4
#define CHUNK     (T_TOTAL / NCHUNK)     // 2048 rows
#define TILE_ROWS 128
#define NTILES    (CHUNK / TILE_ROWS)    // 16
#define NSLICE    256
#define ROW_S     20                     // padded smem row stride (floats)
#define PART_STRIDE 192                  // floats; 192*4 = 768 B = 6 full L2 lines

__device__ float        g_partial[NSLICE * NCHUNK * PART_STRIDE];
__device__ unsigned int g_count[NSLICE];   // zero-init; wraps back to 0 each run

#define FMA2(d, a, b, c) \
    asm("fma.rn.f32x2 %0, %1, %2, %3;" : "=l"(d) : "l"(a), "l"(b), "l"(c))
#define ADD2(d, a, b) \
    asm("add.rn.f32x2 %0, %1, %2;" : "=l"(d) : "l"(a), "l"(b))
#define PACK2_REP(d, x) \
    asm("mov.b64 %0, {%1, %1};" : "=l"(d) : "r"(x))
#define UNPACK2(lo, hi, u) \
    asm("mov.b64 {%0, %1}, %2;" : "=r"(lo), "=r"(hi) : "l"(u))

__global__ __launch_bounds__(320, 3)
void cov_kernel(const float* __restrict__ x, float* __restrict__ out) {
    // tile: 128 rows x ROW_S floats = 2560 floats (10 KB)
    __shared__ float sm[TILE_ROWS * ROW_S];
    __shared__ int   sm_last;

    const int bx    = blockIdx.x;
    const int slice = bx & (NSLICE - 1);
    const int chunk = bx >> 8;                 // 0..3
    const int tid   = threadIdx.x;
    const int warp  = tid >> 5;                // block id 0..9
    const int lane  = tid & 31;

    // (bi,bj), bi<=bj: (0,0)=0 (0,1)=1 (0,2)=2 (0,3)=3 (1,1)=4 (1,2)=5 (1,3)=6 (2,2)=7 (2,3)=8 (3,3)=9
    const int bi  = (warp < 4) ? 0 : (warp < 7) ? 1 : (warp < 9) ? 2 : 3;
    const int off = (bi == 0) ? 0 : (bi == 1) ? 4 : (bi == 2) ? 7 : 9;
    const int bj  = bi + (warp - off);
    const bool diag = (bi == bj);

    const float4* gx = (const float4*)x;
    long base = (long)slice * (T_TOTAL * M_DIM / 4) + (long)chunk * (CHUNK * M_DIM / 4);

    // acc2[p*2+k] holds (S[p][2k], S[p][2k+1]) for the 4x4 block
    unsigned long long acc2[8];
#pragma unroll
    for (int i = 0; i < 8; i++) acc2[i] = 0ull;
    unsigned long long cs01 = 0ull, cs23 = 0ull;   // column sums (diag warps)

    float4 r0, r1;
    if (tid < 256) {
        r0 = gx[base + tid];
        r1 = gx[base + 256 + tid];
    }

    for (int tile = 0; tile < NTILES; ++tile) {
        if (tid < 256) {
            int row0 = tid >> 2, q0 = tid & 3;
            *(float4*)(sm + row0 * ROW_S + q0 * 4) = r0;
            *(float4*)(sm + (row0 + 64) * ROW_S + q0 * 4) = r1;
        }
        __syncthreads();

        if (tile + 1 < NTILES && tid < 256) {
            long nb = base + (long)(tile + 1) * 512;
            r0 = gx[nb + tid];
            r1 = gx[nb + 256 + tid];
        }

#pragma unroll
        for (int r = 0; r < TILE_ROWS / 32; ++r) {
            const int row = r * 32 + lane;
            const float* rp = sm + row * ROW_S;

            ulonglong2 aa = *(const ulonglong2*)(rp + 4 * bi);   // a0..a3 packed
            ulonglong2 cc;
            if (diag) cc = aa;                                    // 1 LDS for diag warps
            else      cc = *(const ulonglong2*)(rp + 4 * bj);

            unsigned int a0, a1, a2, a3;
            UNPACK2(a0, a1, aa.x);
            UNPACK2(a2, a3, aa.y);
            unsigned long long a0p, a1p, a2p, a3p;
            PACK2_REP(a0p, a0);
            PACK2_REP(a1p, a1);
            PACK2_REP(a2p, a2);
            PACK2_REP(a3p, a3);

            FMA2(acc2[0], a0p, cc.x, acc2[0]);
            FMA2(acc2[1], a0p, cc.y, acc2[1]);
            FMA2(acc2[2], a1p, cc.x, acc2[2]);
            FMA2(acc2[3], a1p, cc.y, acc2[3]);
            FMA2(acc2[4], a2p, cc.x, acc2[4]);
            FMA2(acc2[5], a2p, cc.y, acc2[5]);
            FMA2(acc2[6], a3p, cc.x, acc2[6]);
            FMA2(acc2[7], a3p, cc.y, acc2[7]);

            if (diag) {
                ADD2(cs01, cs01, cc.x);
                ADD2(cs23, cs23, cc.y);
            }
        }
        __syncthreads();
    }

    // ---- unpack, warp butterfly reduction (block is warp-uniform) ----
    float acc[16];
#pragma unroll
    for (int p = 0; p < 4; p++) {
        unsigned int u0, u1, u2, u3;
        UNPACK2(u0, u1, acc2[p * 2]);
        UNPACK2(u2, u3, acc2[p * 2 + 1]);
        acc[p * 4 + 0] = __uint_as_float(u0);
        acc[p * 4 + 1] = __uint_as_float(u1);
        acc[p * 4 + 2] = __uint_as_float(u2);
        acc[p * 4 + 3] = __uint_as_float(u3);
    }
    float cs[4];
    {
        unsigned int u0, u1, u2, u3;
        UNPACK2(u0, u1, cs01);
        UNPACK2(u2, u3, cs23);
        cs[0] = __uint_as_float(u0);
        cs[1] = __uint_as_float(u1);
        cs[2] = __uint_as_float(u2);
        cs[3] = __uint_as_float(u3);
    }

#pragma unroll
    for (int o = 16; o >= 1; o >>= 1) {
#pragma unroll
        for (int i = 0; i < 16; i++) acc[i] += __shfl_xor_sync(0xffffffffu, acc[i], o);
        if (diag) {
#pragma unroll
            for (int i = 0; i < 4; i++) cs[i] += __shfl_xor_sync(0xffffffffu, cs[i], o);
        }
    }

    float* part = &g_partial[(slice * NCHUNK + chunk) * PART_STRIDE];
    if (lane < 16) {
        float v = (lane == 0)  ? acc[0]  : (lane == 1)  ? acc[1]  :
                  (lane == 2)  ? acc[2]  : (lane == 3)  ? acc[3]  :
                  (lane == 4)  ? acc[4]  : (lane == 5)  ? acc[5]  :
                  (lane == 6)  ? acc[6]  : (lane == 7)  ? acc[7]  :
                  (lane == 8)  ? acc[8]  : (lane == 9)  ? acc[9]  :
                  (lane == 10) ? acc[10] : (lane == 11) ? acc[11] :
                  (lane == 12) ? acc[12] : (lane == 13) ? acc[13] :
                  (lane == 14) ? acc[14] : acc[15];
        part[warp * 16 + lane] = v;
    }
    if (diag && lane < 4) {
        float v = (lane == 0) ? cs[0] : (lane == 1) ? cs[1] : (lane == 2) ? cs[2] : cs[3];
        part[160 + bi * 4 + lane] = v;       // colsum for m = 4*bi + lane
    }

    // ---- last CTA of this slice folds the 4 chunk partials ----
    __threadfence();                 // release: make scratch writes GPU-visible
    __syncthreads();
    if (tid == 0)
        sm_last = (atomicInc(&g_count[slice], NCHUNK - 1) == NCHUNK - 1);
    __syncthreads();

    if (sm_last) {
        __threadfence();             // acquire: invalidate L1D, see peer writes
        if (tid < 256) {
            int m = tid >> 4;
            int n = tid & 15;
            int fbi = m >> 2, fbj = n >> 2;
            int mm = m, nn = n;
            if (fbi > fbj) { mm = n; nn = m; int t = fbi; fbi = fbj; fbj = t; }
            const int foff = (fbi == 0) ? 0 : (fbi == 1) ? 4 : (fbi == 2) ? 7 : 9;
            const int blk   = foff + (fbj - fbi);
            const int entry = (mm & 3) * 4 + (nn & 3);

            const float* p = &g_partial[slice * NCHUNK * PART_STRIDE];
            float S = 0.f, smv = 0.f, snv = 0.f;
#pragma unroll
            for (int c = 0; c < NCHUNK; ++c) {
                S   += p[c * PART_STRIDE + blk * 16 + entry];
                smv += p[c * PART_STRIDE + 160 + m];
                snv += p[c * PART_STRIDE + 160 + n];
            }
            const float inv_T  = 1.0f / (float)T_TOTAL;
            const float inv_T1 = 1.0f / (float)(T_TOTAL - 1);
            out[slice * 256 + tid] = (S - smv * snv * inv_T) * inv_T1;
        }
    }
}

extern "C" void kernel_launch(void* const* d_in, const int* in_sizes, int n_in,
                              void* d_out, int out_size) {
    const float* x = (const float*)d_in[0];
    float* out = (float*)d_out;
    cov_kernel<<<NSLICE * NCHUNK, 320>>>(x, out);
}